// round 1
// baseline (speedup 1.0000x reference)
#include <cuda_runtime.h>
#include <math.h>

#define NB 8
#define NS 1024
#define NE 1024
#define NH 16
#define ND 64
#define NM (NB*NS)   // 8192 rows

// Scratch (device globals: allocation-free per harness rules)
__device__ float g_qh[NB*NH*NS*ND];   // [B,H,S,D]
__device__ float g_kh[NB*NH*NS*ND];
__device__ float g_vh[NB*NH*NS*ND];
__device__ float g_ctx[NB*NS*NE];     // [B,S,E] (heads concatenated)

// ---------------------------------------------------------------------------
// Projection GEMM: out[b,h,s,e] = sum_d X[b,s,d] * W[h,d,e] + bias[h,e]
// Tile: 64 (M) x 64 (N=full head) x 32 (K). 256 threads, 4x4 micro-tile.
// which: 0->g_qh, 1->g_kh, 2->g_vh
// ---------------------------------------------------------------------------
__global__ __launch_bounds__(256) void proj_kernel(
    const float* __restrict__ X, const float* __restrict__ W,
    const float* __restrict__ bias, int which)
{
    __shared__ __align__(16) float As[64][33];   // pad -> conflict-free column reads
    __shared__ __align__(16) float Bs[32][64];

    float* out = (which == 0) ? g_qh : (which == 1) ? g_kh : g_vh;

    const int h  = blockIdx.y;
    const int m0 = blockIdx.x * 64;
    const int tid = threadIdx.x;
    const int ty = tid >> 4, tx = tid & 15;
    const int r = ty * 4, c = tx * 4;
    const float* Wh = W + (size_t)h * (NE * ND);

    float acc[4][4];
#pragma unroll
    for (int i = 0; i < 4; i++)
#pragma unroll
        for (int j = 0; j < 4; j++) acc[i][j] = 0.f;

    const int arow = tid >> 3;            // 0..31
    const int acol = (tid & 7) * 4;       // 0..28
    const int brow = tid >> 4;            // 0..15
    const int bcol = (tid & 15) * 4;      // 0..60

    for (int k0 = 0; k0 < NE; k0 += 32) {
        float4 a0 = *(const float4*)(X + (size_t)(m0 + arow) * NE + k0 + acol);
        float4 a1 = *(const float4*)(X + (size_t)(m0 + arow + 32) * NE + k0 + acol);
        float4 b0 = *(const float4*)(Wh + (size_t)(k0 + brow) * ND + bcol);
        float4 b1 = *(const float4*)(Wh + (size_t)(k0 + brow + 16) * ND + bcol);

        As[arow][acol+0] = a0.x; As[arow][acol+1] = a0.y;
        As[arow][acol+2] = a0.z; As[arow][acol+3] = a0.w;
        As[arow+32][acol+0] = a1.x; As[arow+32][acol+1] = a1.y;
        As[arow+32][acol+2] = a1.z; As[arow+32][acol+3] = a1.w;
        *(float4*)&Bs[brow][bcol]      = b0;
        *(float4*)&Bs[brow + 16][bcol] = b1;
        __syncthreads();

#pragma unroll
        for (int kk = 0; kk < 32; kk++) {
            float av[4];
#pragma unroll
            for (int i = 0; i < 4; i++) av[i] = As[r + i][kk];
            float4 bv = *(const float4*)&Bs[kk][c];
#pragma unroll
            for (int i = 0; i < 4; i++) {
                acc[i][0] += av[i] * bv.x;
                acc[i][1] += av[i] * bv.y;
                acc[i][2] += av[i] * bv.z;
                acc[i][3] += av[i] * bv.w;
            }
        }
        __syncthreads();
    }

    float4 bb = *(const float4*)(bias + h * ND + c);
#pragma unroll
    for (int i = 0; i < 4; i++) {
        int m = m0 + r + i;
        int b = m >> 10, s = m & 1023;
        float4 v;
        v.x = acc[i][0] + bb.x; v.y = acc[i][1] + bb.y;
        v.z = acc[i][2] + bb.z; v.w = acc[i][3] + bb.w;
        *(float4*)(out + (size_t)(b * NH + h) * (NS * ND) + (size_t)s * ND + c) = v;
    }
}

// ---------------------------------------------------------------------------
// Flash attention per (b,h): 64-row Q tile per block, loop over 16 K/V tiles.
// 256 threads: thread = (row = tid>>2, q4 = tid&3).
//   scores: thread owns k-cols [q4*16, q4*16+16)   (K smem XOR-swizzled by k>>4)
//   output: thread owns e-cols { t*16 + q4*4 .. +3 : t=0..3 } (conflict-free V reads)
// ---------------------------------------------------------------------------
__global__ __launch_bounds__(256) void attn_kernel()
{
    __shared__ __align__(16) float Ks[64][64];   // xor-swizzled columns
    __shared__ __align__(16) float Vs[64][64];
    __shared__ __align__(16) float Ps[64][65];   // pad 65 -> conflict-free col reads

    const int bh = blockIdx.y;
    const int s0 = blockIdx.x * 64;
    const float* Qp = g_qh + (size_t)bh * (NS * ND);
    const float* Kp = g_kh + (size_t)bh * (NS * ND);
    const float* Vp = g_vh + (size_t)bh * (NS * ND);

    const int tid = threadIdx.x;
    const int row = tid >> 2;   // 0..63 (q row in tile)
    const int q4  = tid & 3;

    // Q row into registers (64 floats)
    float qreg[64];
    {
        const float* qs = Qp + (size_t)(s0 + row) * ND;
#pragma unroll
        for (int d4 = 0; d4 < 16; d4++) {
            float4 t = *(const float4*)(qs + d4 * 4);
            qreg[d4*4+0] = t.x; qreg[d4*4+1] = t.y;
            qreg[d4*4+2] = t.z; qreg[d4*4+3] = t.w;
        }
    }

    float m_i = -1e30f, l_i = 0.f;
    float o[16];
#pragma unroll
    for (int i = 0; i < 16; i++) o[i] = 0.f;
    const float scale = 0.125f;  // 1/sqrt(64)

    for (int kt = 0; kt < 16; kt++) {
        // load K (swizzled) and V tiles
#pragma unroll
        for (int i = 0; i < 4; i++) {
            int fi = tid + i * 256;
            int rr = fi >> 4;
            int c4 = fi & 15;
            float4 kv = *(const float4*)(Kp + (size_t)(kt * 64 + rr) * ND + c4 * 4);
            float4 vv = *(const float4*)(Vp + (size_t)(kt * 64 + rr) * ND + c4 * 4);
            *(float4*)&Ks[rr][(c4 ^ (rr >> 4)) * 4] = kv;
            *(float4*)&Vs[rr][c4 * 4] = vv;
        }
        __syncthreads();

        // scores for kl = q4*16 + j, j in [0,16)
        float p[16];
#pragma unroll
        for (int jc = 0; jc < 4; jc++) {
            float a0 = 0.f, a1 = 0.f, a2 = 0.f, a3 = 0.f;
            const int kl0 = q4 * 16 + jc * 4;
#pragma unroll
            for (int d4 = 0; d4 < 16; d4++) {
                const int pc = (d4 ^ q4) * 4;   // matches store swizzle (kl>>4 == q4)
                float4 k0v = *(const float4*)&Ks[kl0 + 0][pc];
                float4 k1v = *(const float4*)&Ks[kl0 + 1][pc];
                float4 k2v = *(const float4*)&Ks[kl0 + 2][pc];
                float4 k3v = *(const float4*)&Ks[kl0 + 3][pc];
                float q0 = qreg[d4*4+0], q1 = qreg[d4*4+1];
                float q2 = qreg[d4*4+2], q3 = qreg[d4*4+3];
                a0 += q0*k0v.x + q1*k0v.y + q2*k0v.z + q3*k0v.w;
                a1 += q0*k1v.x + q1*k1v.y + q2*k1v.z + q3*k1v.w;
                a2 += q0*k2v.x + q1*k2v.y + q2*k2v.z + q3*k2v.w;
                a3 += q0*k3v.x + q1*k3v.y + q2*k3v.z + q3*k3v.w;
            }
            p[jc*4+0] = a0 * scale; p[jc*4+1] = a1 * scale;
            p[jc*4+2] = a2 * scale; p[jc*4+3] = a3 * scale;
        }

        // online softmax (row state replicated across the 4-thread quad)
        float tmax = p[0];
#pragma unroll
        for (int j = 1; j < 16; j++) tmax = fmaxf(tmax, p[j]);
        tmax = fmaxf(tmax, __shfl_xor_sync(0xffffffffu, tmax, 1));
        tmax = fmaxf(tmax, __shfl_xor_sync(0xffffffffu, tmax, 2));
        float m_new = fmaxf(m_i, tmax);
        float alpha = __expf(m_i - m_new);
        float lsum = 0.f;
#pragma unroll
        for (int j = 0; j < 16; j++) { p[j] = __expf(p[j] - m_new); lsum += p[j]; }
        lsum += __shfl_xor_sync(0xffffffffu, lsum, 1);
        lsum += __shfl_xor_sync(0xffffffffu, lsum, 2);
        l_i = l_i * alpha + lsum;
        m_i = m_new;
#pragma unroll
        for (int i = 0; i < 16; i++) o[i] *= alpha;

        // publish P tile
#pragma unroll
        for (int j = 0; j < 16; j++) Ps[row][q4 * 16 + j] = p[j];
        __syncthreads();

        // O += P @ V  (thread e-cols: t*16 + q4*4 .. +3)
#pragma unroll
        for (int k = 0; k < 64; k++) {
            float pk = Ps[row][k];
#pragma unroll
            for (int t = 0; t < 4; t++) {
                float4 vv = *(const float4*)&Vs[k][t * 16 + q4 * 4];
                o[t*4+0] += pk * vv.x; o[t*4+1] += pk * vv.y;
                o[t*4+2] += pk * vv.z; o[t*4+3] += pk * vv.w;
            }
        }
        __syncthreads();
    }

    // normalize + write ctx[b, s, h*64 + e]
    float inv = 1.f / l_i;
    int b = bh >> 4, h = bh & 15;
    float* dst = g_ctx + (size_t)(b * NS + s0 + row) * NE + h * ND;
#pragma unroll
    for (int t = 0; t < 4; t++) {
        float4 v;
        v.x = o[t*4+0] * inv; v.y = o[t*4+1] * inv;
        v.z = o[t*4+2] * inv; v.w = o[t*4+3] * inv;
        *(float4*)(dst + t * 16 + q4 * 4) = v;
    }
}

// ---------------------------------------------------------------------------
// Output GEMM: out[m,n] = sum_k ctx[m,k] * Wo[k,n] + bo[n]
// ---------------------------------------------------------------------------
__global__ __launch_bounds__(256) void out_kernel(
    const float* __restrict__ Wo, const float* __restrict__ bo,
    float* __restrict__ out)
{
    __shared__ __align__(16) float As[64][33];
    __shared__ __align__(16) float Bs[32][64];

    const int n0 = blockIdx.y * 64;
    const int m0 = blockIdx.x * 64;
    const int tid = threadIdx.x;
    const int ty = tid >> 4, tx = tid & 15;
    const int r = ty * 4, c = tx * 4;

    float acc[4][4];
#pragma unroll
    for (int i = 0; i < 4; i++)
#pragma unroll
        for (int j = 0; j < 4; j++) acc[i][j] = 0.f;

    const int arow = tid >> 3;
    const int acol = (tid & 7) * 4;
    const int brow = tid >> 4;
    const int bcol = (tid & 15) * 4;

    for (int k0 = 0; k0 < NE; k0 += 32) {
        float4 a0 = *(const float4*)(g_ctx + (size_t)(m0 + arow) * NE + k0 + acol);
        float4 a1 = *(const float4*)(g_ctx + (size_t)(m0 + arow + 32) * NE + k0 + acol);
        float4 b0 = *(const float4*)(Wo + (size_t)(k0 + brow) * NE + n0 + bcol);
        float4 b1 = *(const float4*)(Wo + (size_t)(k0 + brow + 16) * NE + n0 + bcol);

        As[arow][acol+0] = a0.x; As[arow][acol+1] = a0.y;
        As[arow][acol+2] = a0.z; As[arow][acol+3] = a0.w;
        As[arow+32][acol+0] = a1.x; As[arow+32][acol+1] = a1.y;
        As[arow+32][acol+2] = a1.z; As[arow+32][acol+3] = a1.w;
        *(float4*)&Bs[brow][bcol]      = b0;
        *(float4*)&Bs[brow + 16][bcol] = b1;
        __syncthreads();

#pragma unroll
        for (int kk = 0; kk < 32; kk++) {
            float av[4];
#pragma unroll
            for (int i = 0; i < 4; i++) av[i] = As[r + i][kk];
            float4 bv = *(const float4*)&Bs[kk][c];
#pragma unroll
            for (int i = 0; i < 4; i++) {
                acc[i][0] += av[i] * bv.x;
                acc[i][1] += av[i] * bv.y;
                acc[i][2] += av[i] * bv.z;
                acc[i][3] += av[i] * bv.w;
            }
        }
        __syncthreads();
    }

    float4 bb = *(const float4*)(bo + n0 + c);
#pragma unroll
    for (int i = 0; i < 4; i++) {
        float4 v;
        v.x = acc[i][0] + bb.x; v.y = acc[i][1] + bb.y;
        v.z = acc[i][2] + bb.z; v.w = acc[i][3] + bb.w;
        *(float4*)(out + (size_t)(m0 + r + i) * NE + n0 + c) = v;
    }
}

// ---------------------------------------------------------------------------
extern "C" void kernel_launch(void* const* d_in, const int* in_sizes, int n_in,
                              void* d_out, int out_size)
{
    const float* q  = (const float*)d_in[0];
    const float* k  = (const float*)d_in[1];
    const float* v  = (const float*)d_in[2];
    const float* Wq = (const float*)d_in[3];
    const float* bq = (const float*)d_in[4];
    const float* Wk = (const float*)d_in[5];
    const float* bk = (const float*)d_in[6];
    const float* Wv = (const float*)d_in[7];
    const float* bv = (const float*)d_in[8];
    const float* Wo = (const float*)d_in[9];
    const float* bo = (const float*)d_in[10];
    float* out = (float*)d_out;

    dim3 pgrid(NM / 64, NH);
    proj_kernel<<<pgrid, 256>>>(q, Wq, bq, 0);
    proj_kernel<<<pgrid, 256>>>(k, Wk, bk, 1);
    proj_kernel<<<pgrid, 256>>>(v, Wv, bv, 2);

    attn_kernel<<<dim3(NS / 64, NB * NH), 256>>>();

    out_kernel<<<dim3(NM / 64, NE / 64), 256>>>(Wo, bo, out);
}